// round 13
// baseline (speedup 1.0000x reference)
#include <cuda_runtime.h>
#include <cuda_fp16.h>
#include <cstdint>

#define SSTEPS 8
#define NNODES 50000
#define D 128
#define NE 1600000

#define BM 128
#define PITCH_W 264   // resident W pitch (halves): 528B rows, ldmatrix conflict-free
#define PITCH_ST 24   // A staging pitch (halves)

// ---- device scratch (static; no runtime allocation) ----
__device__ __align__(16) int    g_deg[NNODES];
__device__ __align__(16) int    g_cursor[NNODES];
__device__ __align__(16) int    g_rowbeg[NNODES];
__device__ __align__(16) int    g_col[NE];
__device__ __align__(16) float  g_invdeg[NNODES];
__device__ int                  g_total;
__device__ __align__(16) __half g_Wh[D * 2 * D];                     // [j][k] k<128->W_l else W_r
__device__ __align__(16) __half g_xh[(size_t)NNODES * SSTEPS * D];   // fp16 x, node-major [n][s][d]
__device__ __align__(16) __half g_aggh[(size_t)NNODES * SSTEPS * D]; // fp16 agg, node-major [n][s][d]

// ---------------- CSR build ----------------
__global__ void k_init() {
    int i = blockIdx.x * blockDim.x + threadIdx.x;
    if (i < NNODES) { g_deg[i] = 0; g_cursor[i] = 0; }
    if (i == 0) g_total = 0;
}

__global__ void k_count(const int* __restrict__ ei) {
    int e4 = (blockIdx.x * blockDim.x + threadIdx.x) * 4;
    if (e4 < NE) {
        int4 d = *(const int4*)(ei + NE + e4);
        atomicAdd(&g_deg[d.x], 1);
        atomicAdd(&g_deg[d.y], 1);
        atomicAdd(&g_deg[d.z], 1);
        atomicAdd(&g_deg[d.w], 1);
    }
}

// parallel atomic-offset scan (segment order is irrelevant for a sum)
__global__ void k_scan2() {
    __shared__ int sbuf[256];
    __shared__ int sbase;
    int idx = blockIdx.x * 256 + threadIdx.x;
    int v = (idx < NNODES) ? g_deg[idx] : 0;
    sbuf[threadIdx.x] = v;
    __syncthreads();
    for (int off = 1; off < 256; off <<= 1) {
        int t = (threadIdx.x >= off) ? sbuf[threadIdx.x - off] : 0;
        __syncthreads();
        sbuf[threadIdx.x] += t;
        __syncthreads();
    }
    if (threadIdx.x == 255) sbase = atomicAdd(&g_total, sbuf[255]);
    __syncthreads();
    if (idx < NNODES) {
        g_rowbeg[idx] = sbase + sbuf[threadIdx.x] - v;
        g_invdeg[idx] = 1.0f / (float)max(v, 1);
    }
}

__global__ void k_fill(const int* __restrict__ ei) {
    int e4 = (blockIdx.x * blockDim.x + threadIdx.x) * 4;
    if (e4 < NE) {
        int4 s = *(const int4*)(ei + e4);
        int4 d = *(const int4*)(ei + NE + e4);
        int p;
        p = atomicAdd(&g_cursor[d.x], 1); g_col[g_rowbeg[d.x] + p] = s.x;
        p = atomicAdd(&g_cursor[d.y], 1); g_col[g_rowbeg[d.y] + p] = s.y;
        p = atomicAdd(&g_cursor[d.z], 1); g_col[g_rowbeg[d.z] + p] = s.z;
        p = atomicAdd(&g_cursor[d.w], 1); g_col[g_rowbeg[d.w] + p] = s.w;
    }
}

__global__ void k_wh(const float* __restrict__ Wl, const float* __restrict__ Wr) {
    int i = blockIdx.x * blockDim.x + threadIdx.x;
    if (i < D * 2 * D) {
        int j = i / (2 * D), k = i % (2 * D);
        float v = (k < D) ? Wl[j * D + k] : Wr[j * D + (k - D)];
        g_Wh[i] = __float2half_rn(v);
    }
}

// fp32 [s][n][d] -> fp16 node-major [n][s][d]
__global__ void __launch_bounds__(256) k_tohalf(const float* __restrict__ input) {
    size_t i4 = (size_t)(blockIdx.x * blockDim.x + threadIdx.x) * 4;
    const size_t total = (size_t)SSTEPS * NNODES * D;
    if (i4 < total) {
        float4 v = *(const float4*)(input + i4);
        __half2 h0 = __floats2half2_rn(v.x, v.y);
        __half2 h1 = __floats2half2_rn(v.z, v.w);
        uint2 u;
        u.x = *reinterpret_cast<unsigned*>(&h0);
        u.y = *reinterpret_cast<unsigned*>(&h1);
        int s = (int)(i4 / ((size_t)NNODES * D));
        size_t rem = i4 % ((size_t)NNODES * D);
        int n = (int)(rem / D);
        int d = (int)(rem % D);
        *(uint2*)(g_xh + ((size_t)n * SSTEPS + s) * D + d) = u;
    }
}

// ---------------- gather mean aggregation: one warp per node, ALL 8 steps per edge ----------------
// per edge: 2KB contiguous (8 steps x 128 halves); lane covers slot (s = r*2 + lane/16, q = lane&15)
__global__ void __launch_bounds__(256) k_agg() {
    int n = (blockIdx.x * blockDim.x + threadIdx.x) >> 5;
    if (n >= NNODES) return;
    const int lane = threadIdx.x & 31;
    const int q = lane & 15;
    const int sbase = lane >> 4;

    float acc[4][8];
#pragma unroll
    for (int r = 0; r < 4; r++)
#pragma unroll
        for (int i = 0; i < 8; i++) acc[r][i] = 0.f;

#define ACC_R(r, u) {                                                      \
        __half2 p0 = *reinterpret_cast<__half2*>(&(u).x);                  \
        __half2 p1 = *reinterpret_cast<__half2*>(&(u).y);                  \
        __half2 p2 = *reinterpret_cast<__half2*>(&(u).z);                  \
        __half2 p3 = *reinterpret_cast<__half2*>(&(u).w);                  \
        float2 f0 = __half22float2(p0); float2 f1 = __half22float2(p1);    \
        float2 f2 = __half22float2(p2); float2 f3 = __half22float2(p3);    \
        acc[r][0] += f0.x; acc[r][1] += f0.y; acc[r][2] += f1.x;           \
        acc[r][3] += f1.y; acc[r][4] += f2.x; acc[r][5] += f2.y;           \
        acc[r][6] += f3.x; acc[r][7] += f3.y; }

    const int beg = g_rowbeg[n];
    const int end = beg + g_deg[n];
    const unsigned loff = (unsigned)lane * 8;   // halves offset within 2KB block per round

    int j = beg;
    for (; j + 2 <= end; j += 2) {
        const __half* p0 = g_xh + (size_t)g_col[j]     * (SSTEPS * D);
        const __half* p1 = g_xh + (size_t)g_col[j + 1] * (SSTEPS * D);
        uint4 u00 = *(const uint4*)(p0 + loff);
        uint4 u01 = *(const uint4*)(p0 + 256 + loff);
        uint4 u02 = *(const uint4*)(p0 + 512 + loff);
        uint4 u03 = *(const uint4*)(p0 + 768 + loff);
        uint4 u10 = *(const uint4*)(p1 + loff);
        uint4 u11 = *(const uint4*)(p1 + 256 + loff);
        uint4 u12 = *(const uint4*)(p1 + 512 + loff);
        uint4 u13 = *(const uint4*)(p1 + 768 + loff);
        ACC_R(0, u00) ACC_R(1, u01) ACC_R(2, u02) ACC_R(3, u03)
        ACC_R(0, u10) ACC_R(1, u11) ACC_R(2, u12) ACC_R(3, u13)
    }
    if (j < end) {
        const __half* p0 = g_xh + (size_t)g_col[j] * (SSTEPS * D);
        uint4 u00 = *(const uint4*)(p0 + loff);
        uint4 u01 = *(const uint4*)(p0 + 256 + loff);
        uint4 u02 = *(const uint4*)(p0 + 512 + loff);
        uint4 u03 = *(const uint4*)(p0 + 768 + loff);
        ACC_R(0, u00) ACC_R(1, u01) ACC_R(2, u02) ACC_R(3, u03)
    }
#undef ACC_R

    const float inv = g_invdeg[n];
#pragma unroll
    for (int r = 0; r < 4; r++) {
        int s = r * 2 + sbase;
        __half2 h0 = __floats2half2_rn(acc[r][0] * inv, acc[r][1] * inv);
        __half2 h1 = __floats2half2_rn(acc[r][2] * inv, acc[r][3] * inv);
        __half2 h2 = __floats2half2_rn(acc[r][4] * inv, acc[r][5] * inv);
        __half2 h3 = __floats2half2_rn(acc[r][6] * inv, acc[r][7] * inv);
        uint4 u;
        u.x = *reinterpret_cast<unsigned*>(&h0);
        u.y = *reinterpret_cast<unsigned*>(&h1);
        u.z = *reinterpret_cast<unsigned*>(&h2);
        u.w = *reinterpret_cast<unsigned*>(&h3);
        *(uint4*)(g_aggh + ((size_t)n * SSTEPS + s) * D + q * 8) = u;
    }
}

// ---------------- mma helpers ----------------
#define LDSM4(r0, r1, r2, r3, a) \
    asm volatile("ldmatrix.sync.aligned.m8n8.x4.shared.b16 {%0,%1,%2,%3},[%4];" \
                 : "=r"(r0), "=r"(r1), "=r"(r2), "=r"(r3) : "r"(a))
#define MMA16816(c0, c1, c2, c3, a0, a1, a2, a3, b0, b1) \
    asm volatile("mma.sync.aligned.m16n8k16.row.col.f32.f16.f16.f32 " \
                 "{%0,%1,%2,%3},{%4,%5,%6,%7},{%8,%9},{%0,%1,%2,%3};" \
                 : "+f"(c0), "+f"(c1), "+f"(c2), "+f"(c3) \
                 : "r"(a0), "r"(a1), "r"(a2), "r"(a3), "r"(b0), "r"(b1))

// ---------------- tensor-core GEMM + head (resident W, double-buffered A) ----------------
// grid (ceil(N/128), SSTEPS)
__global__ void __launch_bounds__(256) k_gemm_tc(
    const float* __restrict__ b_l,
    const float* __restrict__ W_fc,
    const float* __restrict__ b_fc,
    float* __restrict__ out)
{
    extern __shared__ __half smem[];
    __half* sW = smem;                         // 128 * 264 halves = 67584 B
    __half* sX = sW + 128 * PITCH_W;           // 2 * 128 * 24 halves = 12288 B
    float*  sYs = (float*)(sX + 2 * BM * PITCH_ST);  // 512 B

    const int s    = blockIdx.y;
    const int nb   = blockIdx.x * BM;
    const int tid  = threadIdx.x;
    const int warp = tid >> 5;
    const int lane = tid & 31;

    float c[16][4];
#pragma unroll
    for (int nt = 0; nt < 16; nt++)
#pragma unroll
        for (int r = 0; r < 4; r++) c[nt][r] = 0.f;

    const int srow = tid >> 1;
    const int koff = (tid & 1) * 8;
    const int n    = nb + srow;
    const bool valid = (n < NNODES);
    const size_t rowbase = ((size_t)n * SSTEPS + s) * D;   // node-major row for this step

    // ---- stage full W once: 128 rows x 32 uint4 = 4096 uint4, 16 per thread ----
#pragma unroll
    for (int i = 0; i < 16; i++) {
        int u = tid * 16 + i;
        int j = u >> 5;
        int kp = (u & 31) * 8;
        uint4 wv = *(const uint4*)(g_Wh + j * (2 * D) + kp);
        *(uint4*)&sW[j * PITCH_W + kp] = wv;
    }

    // prefetch chunk 0 of A (agg)
    uint4 av = make_uint4(0, 0, 0, 0);
    if (valid) av = *(const uint4*)(g_aggh + rowbase + koff);
    *(uint4*)&sX[srow * PITCH_ST + koff] = av;
    __syncthreads();

    const uint32_t sX_u = (uint32_t)__cvta_generic_to_shared(sX);
    const uint32_t sW_u = (uint32_t)__cvta_generic_to_shared(sW);
    const uint32_t a_addr0 = sX_u + (uint32_t)(((warp * 16 + (lane & 15)) * PITCH_ST + (lane >> 4) * 8) * 2);
    const int l8  = lane & 7;
    const int seg = lane >> 3;
    const uint32_t b_row = sW_u + (uint32_t)((((seg >> 1) * 8 + l8) * PITCH_W + (seg & 1) * 8) * 2);

    for (int kc = 0; kc < 16; kc++) {
        if (kc < 15) {
            const int kn = kc + 1;
            av = make_uint4(0, 0, 0, 0);
            if (valid) {
                const __half* src = (kn < 8)
                    ? g_aggh + rowbase + kn * 16 + koff
                    : g_xh   + rowbase + (kn - 8) * 16 + koff;
                av = *(const uint4*)src;
            }
        }

        uint32_t a0, a1, a2, a3;
        LDSM4(a0, a1, a2, a3, a_addr0 + (uint32_t)((kc & 1) * BM * PITCH_ST * 2));

        const uint32_t bcol = (uint32_t)(kc * 16 * 2);
#pragma unroll
        for (int p = 0; p < 8; p++) {
            uint32_t b00, b01, b10, b11;
            LDSM4(b00, b01, b10, b11, b_row + bcol + (uint32_t)(p * 16 * PITCH_W * 2));
            MMA16816(c[2*p][0],   c[2*p][1],   c[2*p][2],   c[2*p][3],   a0, a1, a2, a3, b00, b01);
            MMA16816(c[2*p+1][0], c[2*p+1][1], c[2*p+1][2], c[2*p+1][3], a0, a1, a2, a3, b10, b11);
        }

        if (kc < 15) {
            *(uint4*)&sX[((kc + 1) & 1) * BM * PITCH_ST + srow * PITCH_ST + koff] = av;
            __syncthreads();
        }
    }

    // ---- epilogue: + b_l, write xs, ys dot ----
    const int qt = lane & 3;
    const int r4 = lane >> 2;
    const int m0 = warp * 16 + r4;
    const int m1 = m0 + 8;
    const int n0 = nb + m0;
    const int n1 = nb + m1;
    float ys0 = 0.f, ys1 = 0.f;

#pragma unroll
    for (int nt = 0; nt < 16; nt++) {
        int j = nt * 8 + qt * 2;
        float2 bl = *(const float2*)&b_l[j];
        float2 wf = *(const float2*)&W_fc[j];
        c[nt][0] += bl.x; c[nt][1] += bl.y;
        c[nt][2] += bl.x; c[nt][3] += bl.y;
        ys0 += c[nt][0] * wf.x + c[nt][1] * wf.y;
        ys1 += c[nt][2] * wf.x + c[nt][3] * wf.y;
        if (n0 < NNODES)
            *(float2*)&out[((size_t)s * NNODES + n0) * D + j] = make_float2(c[nt][0], c[nt][1]);
        if (n1 < NNODES)
            *(float2*)&out[((size_t)s * NNODES + n1) * D + j] = make_float2(c[nt][2], c[nt][3]);
    }
    ys0 += __shfl_xor_sync(0xffffffffu, ys0, 1);
    ys0 += __shfl_xor_sync(0xffffffffu, ys0, 2);
    ys1 += __shfl_xor_sync(0xffffffffu, ys1, 1);
    ys1 += __shfl_xor_sync(0xffffffffu, ys1, 2);
    if (qt == 0) { sYs[m0] = ys0; sYs[m1] = ys1; }
    __syncthreads();
    if (tid < BM) {
        int nn = nb + tid;
        if (nn < NNODES)
            out[(size_t)SSTEPS * NNODES * D + (size_t)s * NNODES + nn] = sYs[tid] + b_fc[0];
    }
}

// ---------------- launch: CSR build ∥ conversions, then batched agg + gemm ----------------
extern "C" void kernel_launch(void* const* d_in, const int* in_sizes, int n_in,
                              void* d_out, int out_size) {
    const float* input = (const float*)d_in[0];
    const int*   ei    = (const int*)d_in[1];      // int32 (JAX x64 disabled)
    const float* W_l   = (const float*)d_in[2];
    const float* b_l   = (const float*)d_in[3];
    const float* W_r   = (const float*)d_in[4];
    const float* W_fc  = (const float*)d_in[5];
    const float* b_fc  = (const float*)d_in[6];
    float* out = (float*)d_out;

    static cudaStream_t s2 = nullptr;
    static cudaEvent_t evRoot, evPrep;
    if (!s2) {
        cudaStreamCreateWithFlags(&s2, cudaStreamNonBlocking);
        cudaEventCreateWithFlags(&evRoot, cudaEventDisableTiming);
        cudaEventCreateWithFlags(&evPrep, cudaEventDisableTiming);
    }

    const int smem_bytes = (128 * PITCH_W + 2 * BM * PITCH_ST) * sizeof(__half) + BM * sizeof(float);
    cudaFuncSetAttribute(k_gemm_tc, cudaFuncAttributeMaxDynamicSharedMemorySize, smem_bytes);

    cudaEventRecord(evRoot, 0);
    cudaStreamWaitEvent(s2, evRoot, 0);

    k_wh<<<(D * 2 * D + 255) / 256, 256, 0, s2>>>(W_l, W_r);
    const size_t total = (size_t)SSTEPS * NNODES * D;
    k_tohalf<<<(unsigned)((total / 4 + 255) / 256), 256, 0, s2>>>(input);
    cudaEventRecord(evPrep, s2);

    k_init  <<<(NNODES + 255) / 256, 256>>>();
    k_count <<<(NE / 4 + 255) / 256, 256>>>(ei);
    k_scan2 <<<(NNODES + 255) / 256, 256>>>();
    k_fill  <<<(NE / 4 + 255) / 256, 256>>>(ei);

    cudaStreamWaitEvent(0, evPrep, 0);

    k_agg<<<(NNODES * 32 + 255) / 256, 256>>>();

    dim3 ggrid((NNODES + BM - 1) / BM, SSTEPS);
    k_gemm_tc<<<ggrid, 256, smem_bytes>>>(b_l, W_fc, b_fc, out);
}

// round 14
// speedup vs baseline: 1.1122x; 1.1122x over previous
#include <cuda_runtime.h>
#include <cuda_fp16.h>
#include <cstdint>

#define SSTEPS 8
#define NNODES 50000
#define D 128
#define NE 1600000

#define BM 128
#define PITCH_W 264   // resident W pitch (halves): 528B rows, ldmatrix conflict-free
#define PITCH_ST 24   // A staging pitch (halves)
#define STEPS_PER_BLK 4

// ---- device scratch (static; no runtime allocation) ----
__device__ __align__(16) int    g_deg[NNODES];
__device__ __align__(16) int    g_cursor[NNODES];
__device__ __align__(16) int    g_rowbeg[NNODES];
__device__ __align__(16) int    g_col[NE];
__device__ __align__(16) float  g_invdeg[NNODES];
__device__ int                  g_total;
__device__ __align__(16) __half g_Wh[D * 2 * D];                     // [j][k] k<128->W_l else W_r
__device__ __align__(16) __half g_xh[(size_t)SSTEPS * NNODES * D];   // fp16 x, step-major
__device__ __align__(16) __half g_aggh[(size_t)SSTEPS * NNODES * D]; // fp16 agg, step-major

// ---------------- CSR build ----------------
__global__ void k_init() {
    int i = blockIdx.x * blockDim.x + threadIdx.x;
    if (i < NNODES) { g_deg[i] = 0; g_cursor[i] = 0; }
    if (i == 0) g_total = 0;
}

__global__ void k_count(const int* __restrict__ ei) {
    int e4 = (blockIdx.x * blockDim.x + threadIdx.x) * 4;
    if (e4 < NE) {
        int4 d = *(const int4*)(ei + NE + e4);
        atomicAdd(&g_deg[d.x], 1);
        atomicAdd(&g_deg[d.y], 1);
        atomicAdd(&g_deg[d.z], 1);
        atomicAdd(&g_deg[d.w], 1);
    }
}

__global__ void k_scan2() {
    __shared__ int sbuf[256];
    __shared__ int sbase;
    int idx = blockIdx.x * 256 + threadIdx.x;
    int v = (idx < NNODES) ? g_deg[idx] : 0;
    sbuf[threadIdx.x] = v;
    __syncthreads();
    for (int off = 1; off < 256; off <<= 1) {
        int t = (threadIdx.x >= off) ? sbuf[threadIdx.x - off] : 0;
        __syncthreads();
        sbuf[threadIdx.x] += t;
        __syncthreads();
    }
    if (threadIdx.x == 255) sbase = atomicAdd(&g_total, sbuf[255]);
    __syncthreads();
    if (idx < NNODES) {
        g_rowbeg[idx] = sbase + sbuf[threadIdx.x] - v;
        g_invdeg[idx] = 1.0f / (float)max(v, 1);
    }
}

__global__ void k_fill(const int* __restrict__ ei) {
    int e4 = (blockIdx.x * blockDim.x + threadIdx.x) * 4;
    if (e4 < NE) {
        int4 s = *(const int4*)(ei + e4);
        int4 d = *(const int4*)(ei + NE + e4);
        int p;
        p = atomicAdd(&g_cursor[d.x], 1); g_col[g_rowbeg[d.x] + p] = s.x;
        p = atomicAdd(&g_cursor[d.y], 1); g_col[g_rowbeg[d.y] + p] = s.y;
        p = atomicAdd(&g_cursor[d.z], 1); g_col[g_rowbeg[d.z] + p] = s.z;
        p = atomicAdd(&g_cursor[d.w], 1); g_col[g_rowbeg[d.w] + p] = s.w;
    }
}

__global__ void k_wh(const float* __restrict__ Wl, const float* __restrict__ Wr) {
    int i = blockIdx.x * blockDim.x + threadIdx.x;
    if (i < D * 2 * D) {
        int j = i / (2 * D), k = i % (2 * D);
        float v = (k < D) ? Wl[j * D + k] : Wr[j * D + (k - D)];
        g_Wh[i] = __float2half_rn(v);
    }
}

__global__ void __launch_bounds__(256) k_tohalf(const float* __restrict__ input) {
    size_t i = (size_t)(blockIdx.x * blockDim.x + threadIdx.x) * 4;
    const size_t total = (size_t)SSTEPS * NNODES * D;
    if (i < total) {
        float4 v = *(const float4*)(input + i);
        __half2 h0 = __floats2half2_rn(v.x, v.y);
        __half2 h1 = __floats2half2_rn(v.z, v.w);
        uint2 u;
        u.x = *reinterpret_cast<unsigned*>(&h0);
        u.y = *reinterpret_cast<unsigned*>(&h1);
        *(uint2*)(g_xh + i) = u;
    }
}

// ---------------- gather mean aggregation (warp/node, half-warp/edge) ----------------
__global__ void __launch_bounds__(256) k_agg() {
    int gw = (blockIdx.x * blockDim.x + threadIdx.x) >> 5;
    if (gw >= NNODES) return;
    const int lane = threadIdx.x & 31;
    const int h = lane >> 4;
    const int q = lane & 15;
    const int n = gw;
    const int s = blockIdx.y;
    const __half* bp = g_xh + (size_t)s * NNODES * D + q * 8;

    float acc[8];
#pragma unroll
    for (int i = 0; i < 8; i++) acc[i] = 0.f;

#define ACC_U4(u) {                                                        \
        __half2 p0 = *reinterpret_cast<__half2*>(&u.x);                    \
        __half2 p1 = *reinterpret_cast<__half2*>(&u.y);                    \
        __half2 p2 = *reinterpret_cast<__half2*>(&u.z);                    \
        __half2 p3 = *reinterpret_cast<__half2*>(&u.w);                    \
        float2 f0 = __half22float2(p0); float2 f1 = __half22float2(p1);    \
        float2 f2 = __half22float2(p2); float2 f3 = __half22float2(p3);    \
        acc[0] += f0.x; acc[1] += f0.y; acc[2] += f1.x; acc[3] += f1.y;    \
        acc[4] += f2.x; acc[5] += f2.y; acc[6] += f3.x; acc[7] += f3.y; }

    const int beg = g_rowbeg[n];
    const int end = beg + g_deg[n];
    int j = beg;
    for (; j + 8 <= end; j += 8) {
        int c0 = g_col[j + 0 + h];
        int c1 = g_col[j + 2 + h];
        int c2 = g_col[j + 4 + h];
        int c3 = g_col[j + 6 + h];
        uint4 u0 = *(const uint4*)(bp + (size_t)c0 * D);
        uint4 u1 = *(const uint4*)(bp + (size_t)c1 * D);
        uint4 u2 = *(const uint4*)(bp + (size_t)c2 * D);
        uint4 u3 = *(const uint4*)(bp + (size_t)c3 * D);
        ACC_U4(u0) ACC_U4(u1) ACC_U4(u2) ACC_U4(u3)
    }
    for (; j + 2 <= end; j += 2) {
        int c = g_col[j + h];
        uint4 u = *(const uint4*)(bp + (size_t)c * D);
        ACC_U4(u)
    }
    if (j < end && h == 0) {
        int c = g_col[j];
        uint4 u = *(const uint4*)(bp + (size_t)c * D);
        ACC_U4(u)
    }
#undef ACC_U4

#pragma unroll
    for (int i = 0; i < 8; i++)
        acc[i] += __shfl_down_sync(0xffffffffu, acc[i], 16);

    if (h == 0) {
        float inv = g_invdeg[n];
        __half2 h0 = __floats2half2_rn(acc[0] * inv, acc[1] * inv);
        __half2 h1 = __floats2half2_rn(acc[2] * inv, acc[3] * inv);
        __half2 h2 = __floats2half2_rn(acc[4] * inv, acc[5] * inv);
        __half2 h3 = __floats2half2_rn(acc[6] * inv, acc[7] * inv);
        uint4 u;
        u.x = *reinterpret_cast<unsigned*>(&h0);
        u.y = *reinterpret_cast<unsigned*>(&h1);
        u.z = *reinterpret_cast<unsigned*>(&h2);
        u.w = *reinterpret_cast<unsigned*>(&h3);
        *(uint4*)(g_aggh + ((size_t)s * NNODES + n) * D + q * 8) = u;
    }
}

// ---------------- mma helpers ----------------
#define LDSM4(r0, r1, r2, r3, a) \
    asm volatile("ldmatrix.sync.aligned.m8n8.x4.shared.b16 {%0,%1,%2,%3},[%4];" \
                 : "=r"(r0), "=r"(r1), "=r"(r2), "=r"(r3) : "r"(a))
#define MMA16816(c0, c1, c2, c3, a0, a1, a2, a3, b0, b1) \
    asm volatile("mma.sync.aligned.m16n8k16.row.col.f32.f16.f16.f32 " \
                 "{%0,%1,%2,%3},{%4,%5,%6,%7},{%8,%9},{%0,%1,%2,%3};" \
                 : "+f"(c0), "+f"(c1), "+f"(c2), "+f"(c3) \
                 : "r"(a0), "r"(a1), "r"(a2), "r"(a3), "r"(b0), "r"(b1))

// ---------------- tensor-core GEMM + head: resident W reused across 4 steps ----------------
// grid (ceil(N/128), SSTEPS/STEPS_PER_BLK)
__global__ void __launch_bounds__(256) k_gemm_tc(
    const float* __restrict__ b_l,
    const float* __restrict__ W_fc,
    const float* __restrict__ b_fc,
    float* __restrict__ out)
{
    extern __shared__ __half smem[];
    __half* sW = smem;                         // 128 * 264 halves = 67584 B
    __half* sX = sW + 128 * PITCH_W;           // 2 * 128 * 24 halves = 12288 B
    float*  sYs = (float*)(sX + 2 * BM * PITCH_ST);  // 512 B

    const int nb   = blockIdx.x * BM;
    const int tid  = threadIdx.x;
    const int warp = tid >> 5;
    const int lane = tid & 31;

    const int srow = tid >> 1;
    const int koff = (tid & 1) * 8;
    const int n    = nb + srow;
    const bool valid = (n < NNODES);

    // ---- stage full W once per block: 128 rows x 32 uint4, 16 per thread ----
#pragma unroll
    for (int i = 0; i < 16; i++) {
        int u = tid * 16 + i;
        int j = u >> 5;
        int kp = (u & 31) * 8;
        uint4 wv = *(const uint4*)(g_Wh + j * (2 * D) + kp);
        *(uint4*)&sW[j * PITCH_W + kp] = wv;
    }

    const uint32_t sX_u = (uint32_t)__cvta_generic_to_shared(sX);
    const uint32_t sW_u = (uint32_t)__cvta_generic_to_shared(sW);
    const uint32_t a_addr0 = sX_u + (uint32_t)(((warp * 16 + (lane & 15)) * PITCH_ST + (lane >> 4) * 8) * 2);
    const int l8  = lane & 7;
    const int seg = lane >> 3;
    const uint32_t b_row = sW_u + (uint32_t)((((seg >> 1) * 8 + l8) * PITCH_W + (seg & 1) * 8) * 2);

    const int qt = lane & 3;
    const int r4 = lane >> 2;
    const int m0 = warp * 16 + r4;
    const int m1 = m0 + 8;
    const int n0 = nb + m0;
    const int n1 = nb + m1;

    for (int ss = 0; ss < STEPS_PER_BLK; ss++) {
        const int s = blockIdx.y * STEPS_PER_BLK + ss;
        const __half* ab = g_aggh + (size_t)s * NNODES * D;
        const __half* xb = g_xh   + (size_t)s * NNODES * D;

        float c[16][4];
#pragma unroll
        for (int nt = 0; nt < 16; nt++)
#pragma unroll
            for (int r = 0; r < 4; r++) c[nt][r] = 0.f;

        // prefetch chunk 0 of A (agg); the first-iteration sync also covers W staging
        uint4 av = make_uint4(0, 0, 0, 0);
        if (valid) av = *(const uint4*)(ab + (size_t)n * D + koff);
        *(uint4*)&sX[srow * PITCH_ST + koff] = av;
        __syncthreads();

        for (int kc = 0; kc < 16; kc++) {
            if (kc < 15) {
                const int kn = kc + 1;
                av = make_uint4(0, 0, 0, 0);
                if (valid) {
                    const __half* src = (kn < 8)
                        ? ab + (size_t)n * D + kn * 16 + koff
                        : xb + (size_t)n * D + (kn - 8) * 16 + koff;
                    av = *(const uint4*)src;
                }
            }

            uint32_t a0, a1, a2, a3;
            LDSM4(a0, a1, a2, a3, a_addr0 + (uint32_t)((kc & 1) * BM * PITCH_ST * 2));

            const uint32_t bcol = (uint32_t)(kc * 16 * 2);
#pragma unroll
            for (int p = 0; p < 8; p++) {
                uint32_t b00, b01, b10, b11;
                LDSM4(b00, b01, b10, b11, b_row + bcol + (uint32_t)(p * 16 * PITCH_W * 2));
                MMA16816(c[2*p][0],   c[2*p][1],   c[2*p][2],   c[2*p][3],   a0, a1, a2, a3, b00, b01);
                MMA16816(c[2*p+1][0], c[2*p+1][1], c[2*p+1][2], c[2*p+1][3], a0, a1, a2, a3, b10, b11);
            }

            if (kc < 15) {
                *(uint4*)&sX[((kc + 1) & 1) * BM * PITCH_ST + srow * PITCH_ST + koff] = av;
                __syncthreads();
            }
        }

        // ---- epilogue for this step ----
        float ys0 = 0.f, ys1 = 0.f;
#pragma unroll
        for (int nt = 0; nt < 16; nt++) {
            int j = nt * 8 + qt * 2;
            float2 bl = *(const float2*)&b_l[j];
            float2 wf = *(const float2*)&W_fc[j];
            c[nt][0] += bl.x; c[nt][1] += bl.y;
            c[nt][2] += bl.x; c[nt][3] += bl.y;
            ys0 += c[nt][0] * wf.x + c[nt][1] * wf.y;
            ys1 += c[nt][2] * wf.x + c[nt][3] * wf.y;
            if (n0 < NNODES)
                *(float2*)&out[((size_t)s * NNODES + n0) * D + j] = make_float2(c[nt][0], c[nt][1]);
            if (n1 < NNODES)
                *(float2*)&out[((size_t)s * NNODES + n1) * D + j] = make_float2(c[nt][2], c[nt][3]);
        }
        ys0 += __shfl_xor_sync(0xffffffffu, ys0, 1);
        ys0 += __shfl_xor_sync(0xffffffffu, ys0, 2);
        ys1 += __shfl_xor_sync(0xffffffffu, ys1, 1);
        ys1 += __shfl_xor_sync(0xffffffffu, ys1, 2);
        if (qt == 0) { sYs[m0] = ys0; sYs[m1] = ys1; }
        __syncthreads();
        if (tid < BM) {
            int nn = nb + tid;
            if (nn < NNODES)
                out[(size_t)SSTEPS * NNODES * D + (size_t)s * NNODES + nn] = sYs[tid] + b_fc[0];
        }
        __syncthreads();   // protect sYs/sX reuse in the next step
    }
}

// ---------------- launch: CSR build ∥ conversions, then batched agg + gemm ----------------
extern "C" void kernel_launch(void* const* d_in, const int* in_sizes, int n_in,
                              void* d_out, int out_size) {
    const float* input = (const float*)d_in[0];
    const int*   ei    = (const int*)d_in[1];      // int32 (JAX x64 disabled)
    const float* W_l   = (const float*)d_in[2];
    const float* b_l   = (const float*)d_in[3];
    const float* W_r   = (const float*)d_in[4];
    const float* W_fc  = (const float*)d_in[5];
    const float* b_fc  = (const float*)d_in[6];
    float* out = (float*)d_out;

    static cudaStream_t s2 = nullptr;
    static cudaEvent_t evRoot, evPrep;
    if (!s2) {
        cudaStreamCreateWithFlags(&s2, cudaStreamNonBlocking);
        cudaEventCreateWithFlags(&evRoot, cudaEventDisableTiming);
        cudaEventCreateWithFlags(&evPrep, cudaEventDisableTiming);
    }

    const int smem_bytes = (128 * PITCH_W + 2 * BM * PITCH_ST) * sizeof(__half) + BM * sizeof(float);
    cudaFuncSetAttribute(k_gemm_tc, cudaFuncAttributeMaxDynamicSharedMemorySize, smem_bytes);

    cudaEventRecord(evRoot, 0);
    cudaStreamWaitEvent(s2, evRoot, 0);

    k_wh<<<(D * 2 * D + 255) / 256, 256, 0, s2>>>(W_l, W_r);
    const size_t total = (size_t)SSTEPS * NNODES * D;
    k_tohalf<<<(unsigned)((total / 4 + 255) / 256), 256, 0, s2>>>(input);
    cudaEventRecord(evPrep, s2);

    k_init  <<<(NNODES + 255) / 256, 256>>>();
    k_count <<<(NE / 4 + 255) / 256, 256>>>(ei);
    k_scan2 <<<(NNODES + 255) / 256, 256>>>();
    k_fill  <<<(NE / 4 + 255) / 256, 256>>>(ei);

    cudaStreamWaitEvent(0, evPrep, 0);

    dim3 agrid((NNODES * 32 + 255) / 256, SSTEPS);
    k_agg<<<agrid, 256>>>();

    dim3 ggrid((NNODES + BM - 1) / BM, SSTEPS / STEPS_PER_BLK);
    k_gemm_tc<<<ggrid, 256, smem_bytes>>>(b_l, W_fc, b_fc, out);
}